// round 2
// baseline (speedup 1.0000x reference)
#include <cuda_runtime.h>
#include <cstdint>

#define NF     12
#define NCOMB  781           // C(12,2)+C(12,3)+C(12,4)
#define NCOLS  793
#define NROWS  32768
#define TILE   128           // rows per block (y)
#define STAGE  32            // rows staged in shared per sync

// ---------------------------------------------------------------------------
// Compile-time combination table: 4 packed nibble-capable byte indices per
// combo (lexicographic, matching itertools.combinations). Unused slots hold
// sentinel 12 -> s_sh[r][12..15] = 1.0f.
// ---------------------------------------------------------------------------
struct Tbl { uint32_t v[NCOMB]; };

constexpr Tbl make_tbl() {
    Tbl t{};
    int p = 0;
    for (int size = 2; size <= 4; ++size) {
        int c[4] = {0, 1, 2, 3};
        for (int j = 0; j < size; ++j) c[j] = j;
        while (true) {
            uint32_t w = 0;
            for (int j = 0; j < 4; ++j) {
                uint32_t b = (j < size) ? (uint32_t)c[j] : 12u;
                w |= b << (8 * j);
            }
            t.v[p++] = w;
            int j = size - 1;
            while (j >= 0 && c[j] == NF - size + j) --j;
            if (j < 0) break;
            ++c[j];
            for (int k = j + 1; k < size; ++k) c[k] = c[k - 1] + 1;
        }
    }
    return t;
}

__device__ const Tbl d_tbl = make_tbl();

// scratch: s_i = 1 - (1 - x_i)^lambda, row-major [NROWS][NF]  (1.5 MB, L2-hot)
__device__ float g_s[NROWS * NF];

// ---------------------------------------------------------------------------
// Kernel 1: materialize s (trivial, ~400K threads)
// ---------------------------------------------------------------------------
__global__ void prep_kernel(const float* __restrict__ x,
                            const float* __restrict__ lam_p)
{
    const int i = blockIdx.x * blockDim.x + threadIdx.x;
    if (i < NROWS * NF) {
        const float lam = __ldg(lam_p);
        g_s[i] = 1.0f - __powf(1.0f - x[i], lam);
    }
}

// ---------------------------------------------------------------------------
// Kernel 2: column-stationary sweep.
//   blockDim = (32, 8). Each thread owns ONE output column (table decoded
//   once), and loops over TILE rows. Shared stages STAGE rows of s; all lanes
//   of a warp read the SAME row -> LDS broadcast, conflict-free.
// ---------------------------------------------------------------------------
__global__ __launch_bounds__(256, 8)
void main_kernel(const float* __restrict__ x,
                 const float* __restrict__ lam_p,
                 float* __restrict__ out)
{
    __shared__ float s_sh[STAGE][16];

    const float inv = 1.0f / __ldg(lam_p);

    const int col    = blockIdx.x * 32 + threadIdx.x;
    const bool valid = (col < NCOLS);
    const bool copy  = (col < NF);

    // decode combo ONCE per thread
    const int  ci = (valid && !copy) ? (col - NF) : 0;
    const uint32_t w = d_tbl.v[ci];
    const int i0 =  w        & 15u;
    const int i1 = (w >>  8) & 15u;
    const int i2 = (w >> 16) & 15u;
    const int i3 = (w >> 24) & 15u;

    const int row0 = blockIdx.y * TILE;
    const int tid  = threadIdx.y * 32 + threadIdx.x;

    for (int t0 = 0; t0 < TILE; t0 += STAGE) {
        __syncthreads();
        // stage STAGE rows of s into shared (512 entries, 2 per thread)
        #pragma unroll
        for (int e = tid; e < STAGE * 16; e += 256) {
            const int r = e >> 4;
            const int f = e & 15;
            s_sh[r][f] = (f < NF) ? g_s[(row0 + t0 + r) * NF + f] : 1.0f;
        }
        __syncthreads();

        #pragma unroll
        for (int k = 0; k < STAGE / 8; ++k) {
            const int rl = threadIdx.y * (STAGE / 8) + k;   // local row
            const int gr = row0 + t0 + rl;                  // global row
            const float* sp = s_sh[rl];

            float v;
            if (copy) {
                v = x[gr * NF + col];
            } else {
                const float p = sp[i0] * sp[i1] * sp[i2] * sp[i3];
                v = 1.0f - __powf(1.0f - p, inv);
            }
            if (valid) out[(size_t)gr * NCOLS + col] = v;
        }
    }
}

extern "C" void kernel_launch(void* const* d_in, const int* in_sizes, int n_in,
                              void* d_out, int out_size)
{
    const float* x   = (const float*)d_in[0];
    const float* lam = (const float*)d_in[1];
    float*       out = (float*)d_out;

    prep_kernel<<<(NROWS * NF + 255) / 256, 256>>>(x, lam);

    dim3 grid((NCOLS + 31) / 32, NROWS / TILE);   // 25 x 256
    dim3 bdim(32, 8);
    main_kernel<<<grid, bdim>>>(x, lam, out);
}